// round 2
// baseline (speedup 1.0000x reference)
#include <cuda_runtime.h>

// Problem constants (fixed-shape problem; runtime values derived from in_sizes)
#define NMAX 100000
#define EMAX 1600000

// ---------------- device scratch (static: no allocation allowed) -------------
__device__ int   g_cnt[NMAX];        // in-degree (excl self loop)
__device__ int   g_cursor[NMAX];     // CSR fill cursors
__device__ int   g_rowptr[NMAX];     // exclusive prefix of g_cnt
__device__ float g_dis[NMAX];        // rsqrt(deg) with deg = indeg+1
__device__ int   g_col[EMAX];        // CSR column (src) indices
__device__ int   g_partials[256];    // scan partials
__device__ float g_buf0[(size_t)NMAX * 128];
__device__ float g_buf1[(size_t)NMAX * 128];
__device__ float g_buf3[(size_t)NMAX * 16];

// ---------------- graph preprocessing ----------------------------------------
__global__ void init_k(int n) {
    int i = blockIdx.x * blockDim.x + threadIdx.x;
    if (i < n) { g_cnt[i] = 0; g_cursor[i] = 0; }
}

__global__ void count_k(const int* __restrict__ dst, int e) {
    int i = blockIdx.x * blockDim.x + threadIdx.x;
    if (i < e) atomicAdd(&g_cnt[dst[i]], 1);
}

// block-wise exclusive scan, 512 elems/block
__global__ void scan1_k(int n) {
    __shared__ int s[512];
    int tid = threadIdx.x;
    int i = blockIdx.x * 512 + tid;
    int v = (i < n) ? g_cnt[i] : 0;
    s[tid] = v;
    __syncthreads();
    for (int off = 1; off < 512; off <<= 1) {
        int t = (tid >= off) ? s[tid - off] : 0;
        __syncthreads();
        s[tid] += t;
        __syncthreads();
    }
    if (i < n) g_rowptr[i] = s[tid] - v;       // exclusive within block
    if (tid == 511) g_partials[blockIdx.x] = s[511];
}

__global__ void scan2_k(int nb) {
    __shared__ int s[256];
    int tid = threadIdx.x;
    int v = (tid < nb) ? g_partials[tid] : 0;
    s[tid] = v;
    __syncthreads();
    for (int off = 1; off < 256; off <<= 1) {
        int t = (tid >= off) ? s[tid - off] : 0;
        __syncthreads();
        s[tid] += t;
        __syncthreads();
    }
    if (tid < nb) g_partials[tid] = s[tid] - v;  // exclusive block offsets
}

__global__ void scan3_k(int n) {
    int i = blockIdx.x * 512 + threadIdx.x;
    if (i < n) g_rowptr[i] += g_partials[blockIdx.x];
}

__global__ void dis_k(int n) {
    int i = blockIdx.x * blockDim.x + threadIdx.x;
    if (i < n) g_dis[i] = rsqrtf((float)(g_cnt[i] + 1));   // +1: self loop
}

__global__ void fill_k(const int* __restrict__ src, const int* __restrict__ dst, int e) {
    int i = blockIdx.x * blockDim.x + threadIdx.x;
    if (i < e) {
        int d = dst[i];
        int p = atomicAdd(&g_cursor[d], 1);
        g_col[g_rowptr[d] + p] = src[i];
    }
}

// ---------------- GEMM: out[m,:] = dis[m] * (A[m,:] @ W)  (K=128, Nout=128) --
__global__ __launch_bounds__(256)
void gemm128_k(const float* __restrict__ A, const float* __restrict__ W,
               float* __restrict__ out, int M) {
    __shared__ float As[8][132];   // [BK][BM+pad]
    __shared__ float Bs[8][128];   // [BK][BN]
    const int t  = threadIdx.x;
    const int bm = blockIdx.x * 128;
    const int a_row = t >> 1, a_col = (t & 1) * 4;
    const int b_row = t >> 5, b_col = (t & 31) * 4;
    const int tx = t & 15, ty = t >> 4;

    float acc[8][8];
#pragma unroll
    for (int i = 0; i < 8; i++)
#pragma unroll
        for (int j = 0; j < 8; j++) acc[i][j] = 0.0f;

    for (int k0 = 0; k0 < 128; k0 += 8) {
        float4 av = make_float4(0.f, 0.f, 0.f, 0.f);
        int gm = bm + a_row;
        if (gm < M)
            av = *reinterpret_cast<const float4*>(A + (size_t)gm * 128 + k0 + a_col);
        As[0][0] = As[0][0];  // no-op (keeps layout explicit below)
        As[a_col + 0][a_row] = av.x;
        As[a_col + 1][a_row] = av.y;
        As[a_col + 2][a_row] = av.z;
        As[a_col + 3][a_row] = av.w;
        *reinterpret_cast<float4*>(&Bs[b_row][b_col]) =
            *reinterpret_cast<const float4*>(W + (size_t)(k0 + b_row) * 128 + b_col);
        __syncthreads();
#pragma unroll
        for (int k = 0; k < 8; k++) {
            float af[8], bf[8];
#pragma unroll
            for (int i = 0; i < 8; i++) af[i] = As[k][ty * 8 + i];
#pragma unroll
            for (int j = 0; j < 8; j++) bf[j] = Bs[k][tx * 8 + j];
#pragma unroll
            for (int i = 0; i < 8; i++)
#pragma unroll
                for (int j = 0; j < 8; j++)
                    acc[i][j] = fmaf(af[i], bf[j], acc[i][j]);
        }
        __syncthreads();
    }

#pragma unroll
    for (int i = 0; i < 8; i++) {
        int gm = bm + ty * 8 + i;
        if (gm >= M) continue;
        float d = g_dis[gm];
        float* op = out + (size_t)gm * 128 + tx * 8;
        float4 v0, v1;
        v0.x = d * acc[i][0]; v0.y = d * acc[i][1]; v0.z = d * acc[i][2]; v0.w = d * acc[i][3];
        v1.x = d * acc[i][4]; v1.y = d * acc[i][5]; v1.z = d * acc[i][6]; v1.w = d * acc[i][7];
        *reinterpret_cast<float4*>(op)     = v0;
        *reinterpret_cast<float4*>(op + 4) = v1;
    }
}

// ---------------- aggregation D=128: one warp per node -----------------------
// out[i] = maybe_relu( dis[i] * (g[i] + sum_{s in adj(i)} g[s]) + b )
__global__ __launch_bounds__(256)
void agg128_k(const float* __restrict__ g, const float* __restrict__ b,
              float* __restrict__ out, int n, int relu) {
    int warp = (blockIdx.x * blockDim.x + threadIdx.x) >> 5;
    int lane = threadIdx.x & 31;
    if (warp >= n) return;

    float4 acc = *(reinterpret_cast<const float4*>(g + (size_t)warp * 128) + lane); // self loop
    int start = g_rowptr[warp];
    int c     = g_cnt[warp];
    int i = 0;
    for (; i + 4 <= c; i += 4) {
        int s0 = g_col[start + i];
        int s1 = g_col[start + i + 1];
        int s2 = g_col[start + i + 2];
        int s3 = g_col[start + i + 3];
        float4 v0 = *(reinterpret_cast<const float4*>(g + (size_t)s0 * 128) + lane);
        float4 v1 = *(reinterpret_cast<const float4*>(g + (size_t)s1 * 128) + lane);
        float4 v2 = *(reinterpret_cast<const float4*>(g + (size_t)s2 * 128) + lane);
        float4 v3 = *(reinterpret_cast<const float4*>(g + (size_t)s3 * 128) + lane);
        acc.x += (v0.x + v1.x) + (v2.x + v3.x);
        acc.y += (v0.y + v1.y) + (v2.y + v3.y);
        acc.z += (v0.z + v1.z) + (v2.z + v3.z);
        acc.w += (v0.w + v1.w) + (v2.w + v3.w);
    }
    for (; i < c; i++) {
        int s = g_col[start + i];
        float4 v = *(reinterpret_cast<const float4*>(g + (size_t)s * 128) + lane);
        acc.x += v.x; acc.y += v.y; acc.z += v.z; acc.w += v.w;
    }
    float d = g_dis[warp];
    float4 bb = *(reinterpret_cast<const float4*>(b) + lane);
    float4 r;
    r.x = fmaf(d, acc.x, bb.x);
    r.y = fmaf(d, acc.y, bb.y);
    r.z = fmaf(d, acc.z, bb.z);
    r.w = fmaf(d, acc.w, bb.w);
    if (relu) {
        r.x = fmaxf(r.x, 0.f); r.y = fmaxf(r.y, 0.f);
        r.z = fmaxf(r.z, 0.f); r.w = fmaxf(r.w, 0.f);
    }
    *(reinterpret_cast<float4*>(out + (size_t)warp * 128) + lane) = r;
}

// ---------------- GEMM small: out[m,:] = dis[m]*(A[m,:] @ W3), Nout=16 -------
__global__ __launch_bounds__(256)
void gemm16_k(const float* __restrict__ A, const float* __restrict__ W,
              float* __restrict__ out, int M) {
    __shared__ float in_s[64][132];
    __shared__ float Ws[128 * 16];
    int t  = threadIdx.x;
    int br = blockIdx.x * 64;
#pragma unroll
    for (int i = 0; i < 8; i++) Ws[t + 256 * i] = W[t + 256 * i];
#pragma unroll
    for (int it = 0; it < 8; it++) {
        int flat = t + 256 * it;          // float4 index
        int row = flat >> 5, c4 = flat & 31;
        int gm = br + row;
        float4 v = make_float4(0.f, 0.f, 0.f, 0.f);
        if (gm < M) v = *(reinterpret_cast<const float4*>(A + (size_t)gm * 128) + c4);
        *reinterpret_cast<float4*>(&in_s[row][c4 * 4]) = v;
    }
    __syncthreads();
    int r = t >> 2, nq = (t & 3) * 4;
    int gm = br + r;
    float4 acc = make_float4(0.f, 0.f, 0.f, 0.f);
#pragma unroll
    for (int k = 0; k < 128; k++) {
        float a = in_s[r][k];
        float4 w = *reinterpret_cast<const float4*>(&Ws[k * 16 + nq]);
        acc.x = fmaf(a, w.x, acc.x);
        acc.y = fmaf(a, w.y, acc.y);
        acc.z = fmaf(a, w.z, acc.z);
        acc.w = fmaf(a, w.w, acc.w);
    }
    if (gm < M) {
        float d = g_dis[gm];
        float4 o;
        o.x = d * acc.x; o.y = d * acc.y; o.z = d * acc.z; o.w = d * acc.w;
        *reinterpret_cast<float4*>(out + (size_t)gm * 16 + nq) = o;
    }
}

// ---------------- aggregation D=16: 4 threads per node (no relu) -------------
__global__ __launch_bounds__(256)
void agg16_k(const float* __restrict__ g, const float* __restrict__ b,
             float* __restrict__ out, int n) {
    int gt = blockIdx.x * blockDim.x + threadIdx.x;
    int node = gt >> 2, q = gt & 3;
    if (node >= n) return;
    float4 acc = *reinterpret_cast<const float4*>(g + (size_t)node * 16 + q * 4); // self loop
    int start = g_rowptr[node];
    int c     = g_cnt[node];
    for (int i = 0; i < c; i++) {
        int s = g_col[start + i];
        float4 v = *reinterpret_cast<const float4*>(g + (size_t)s * 16 + q * 4);
        acc.x += v.x; acc.y += v.y; acc.z += v.z; acc.w += v.w;
    }
    float d = g_dis[node];
    float4 bb = *reinterpret_cast<const float4*>(b + q * 4);
    float4 r;
    r.x = fmaf(d, acc.x, bb.x);
    r.y = fmaf(d, acc.y, bb.y);
    r.z = fmaf(d, acc.z, bb.z);
    r.w = fmaf(d, acc.w, bb.w);
    *reinterpret_cast<float4*>(out + (size_t)node * 16 + q * 4) = r;
}

// ---------------- launch ------------------------------------------------------
extern "C" void kernel_launch(void* const* d_in, const int* in_sizes, int n_in,
                              void* d_out, int out_size) {
    const float* x  = (const float*)d_in[0];
    const int*   ei = (const int*)d_in[1];
    const float* W1 = (const float*)d_in[2];
    const float* b1 = (const float*)d_in[3];
    const float* W2 = (const float*)d_in[4];
    const float* b2 = (const float*)d_in[5];
    const float* W3 = (const float*)d_in[6];
    const float* b3 = (const float*)d_in[7];
    float* out = (float*)d_out;

    int n = in_sizes[0] / 128;   // 100000
    int e = in_sizes[1] / 2;     // 1600000
    const int* src = ei;
    const int* dst = ei + e;

    float *buf0, *buf1, *buf3;
    cudaGetSymbolAddress((void**)&buf0, g_buf0);
    cudaGetSymbolAddress((void**)&buf1, g_buf1);
    cudaGetSymbolAddress((void**)&buf3, g_buf3);

    int nb512 = (n + 511) / 512;

    // CSR build + normalization
    init_k <<<(n + 255) / 256, 256>>>(n);
    count_k<<<(e + 255) / 256, 256>>>(dst, e);
    scan1_k<<<nb512, 512>>>(n);
    scan2_k<<<1, 256>>>(nb512);
    scan3_k<<<nb512, 512>>>(n);
    dis_k  <<<(n + 255) / 256, 256>>>(n);
    fill_k <<<(e + 255) / 256, 256>>>(src, dst, e);

    // Layer 1
    gemm128_k<<<(n + 127) / 128, 256>>>(x, W1, buf0, n);
    agg128_k <<<(n + 7) / 8, 256>>>(buf0, b1, buf1, n, 1);
    // Layer 2
    gemm128_k<<<(n + 127) / 128, 256>>>(buf1, W2, buf0, n);
    agg128_k <<<(n + 7) / 8, 256>>>(buf0, b2, buf1, n, 1);
    // Layer 3
    gemm16_k <<<(n + 63) / 64, 256>>>(buf1, W3, buf3, n);
    agg16_k  <<<(n * 4 + 255) / 256, 256>>>(buf3, b3, out, n);
}

// round 3
// speedup vs baseline: 1.0059x; 1.0059x over previous
#include <cuda_runtime.h>

// Problem constants (fixed-shape problem; runtime values derived from in_sizes)
#define NMAX 100000
#define EMAX 1600000

// ---------------- device scratch (static: no allocation allowed) -------------
__device__ int   g_cnt[NMAX];        // in-degree (excl self loop)
__device__ int   g_cursor[NMAX];     // CSR fill cursors
__device__ int   g_rowptr[NMAX];     // exclusive prefix of g_cnt
__device__ float g_dis[NMAX];        // rsqrt(deg) with deg = indeg+1
__device__ int   g_col[EMAX];        // CSR column (src) indices
__device__ int   g_partials[256];    // scan partials
__device__ float g_buf0[(size_t)NMAX * 128];
__device__ float g_buf1[(size_t)NMAX * 128];
__device__ float g_buf3[(size_t)NMAX * 16];

// ---------------- packed fp32x2 helpers (Blackwell FFMA2 pipe) ---------------
__device__ __forceinline__ unsigned long long pk2(float x, float y) {
    unsigned long long r;
    asm("mov.b64 %0, {%1, %2};" : "=l"(r) : "f"(x), "f"(y));
    return r;
}
__device__ __forceinline__ void fma2(unsigned long long& d,
                                     unsigned long long a, unsigned long long b) {
    asm("fma.rn.f32x2 %0, %1, %2, %0;" : "+l"(d) : "l"(a), "l"(b));
}
__device__ __forceinline__ void upk2(unsigned long long v, float& x, float& y) {
    asm("mov.b64 {%0, %1}, %2;" : "=f"(x), "=f"(y) : "l"(v));
}

// ---------------- graph preprocessing ----------------------------------------
__global__ void init_k(int n) {
    int i = blockIdx.x * blockDim.x + threadIdx.x;
    if (i < n) { g_cnt[i] = 0; g_cursor[i] = 0; }
}

__global__ void count_k(const int* __restrict__ dst, int e) {
    int i = blockIdx.x * blockDim.x + threadIdx.x;
    if (i < e) atomicAdd(&g_cnt[dst[i]], 1);
}

// block-wise exclusive scan, 512 elems/block
__global__ void scan1_k(int n) {
    __shared__ int s[512];
    int tid = threadIdx.x;
    int i = blockIdx.x * 512 + tid;
    int v = (i < n) ? g_cnt[i] : 0;
    s[tid] = v;
    __syncthreads();
    for (int off = 1; off < 512; off <<= 1) {
        int t = (tid >= off) ? s[tid - off] : 0;
        __syncthreads();
        s[tid] += t;
        __syncthreads();
    }
    if (i < n) g_rowptr[i] = s[tid] - v;       // exclusive within block
    if (tid == 511) g_partials[blockIdx.x] = s[511];
}

__global__ void scan2_k(int nb) {
    __shared__ int s[256];
    int tid = threadIdx.x;
    int v = (tid < nb) ? g_partials[tid] : 0;
    s[tid] = v;
    __syncthreads();
    for (int off = 1; off < 256; off <<= 1) {
        int t = (tid >= off) ? s[tid - off] : 0;
        __syncthreads();
        s[tid] += t;
        __syncthreads();
    }
    if (tid < nb) g_partials[tid] = s[tid] - v;  // exclusive block offsets
}

__global__ void scan3_k(int n) {
    int i = blockIdx.x * 512 + threadIdx.x;
    if (i < n) g_rowptr[i] += g_partials[blockIdx.x];
}

__global__ void dis_k(int n) {
    int i = blockIdx.x * blockDim.x + threadIdx.x;
    if (i < n) g_dis[i] = rsqrtf((float)(g_cnt[i] + 1));   // +1: self loop
}

__global__ void fill_k(const int* __restrict__ src, const int* __restrict__ dst, int e) {
    int i = blockIdx.x * blockDim.x + threadIdx.x;
    if (i < e) {
        int d = dst[i];
        int p = atomicAdd(&g_cursor[d], 1);
        g_col[g_rowptr[d] + p] = src[i];
    }
}

// ---------------- GEMM: out[m,:] = dis[m] * (A[m,:] @ W)  (K=128, Nout=128) --
// 128x128 blocktile, 8x8 per-thread tile computed as 8x4 packed f32x2 accums.
__global__ __launch_bounds__(256)
void gemm128_k(const float* __restrict__ A, const float* __restrict__ W,
               float* __restrict__ out, int M) {
    __shared__ float As[8][132];   // [BK][BM+pad]
    __shared__ float Bs[8][128];   // [BK][BN]
    const int t  = threadIdx.x;
    const int bm = blockIdx.x * 128;
    const int a_row = t >> 1, a_col = (t & 1) * 4;
    const int b_row = t >> 5, b_col = (t & 31) * 4;
    const int tx = t & 15, ty = t >> 4;

    unsigned long long acc2[8][4];
#pragma unroll
    for (int i = 0; i < 8; i++)
#pragma unroll
        for (int j = 0; j < 4; j++) acc2[i][j] = 0ULL;

    for (int k0 = 0; k0 < 128; k0 += 8) {
        float4 av = make_float4(0.f, 0.f, 0.f, 0.f);
        int gm = bm + a_row;
        if (gm < M)
            av = *reinterpret_cast<const float4*>(A + (size_t)gm * 128 + k0 + a_col);
        As[a_col + 0][a_row] = av.x;
        As[a_col + 1][a_row] = av.y;
        As[a_col + 2][a_row] = av.z;
        As[a_col + 3][a_row] = av.w;
        *reinterpret_cast<float4*>(&Bs[b_row][b_col]) =
            *reinterpret_cast<const float4*>(W + (size_t)(k0 + b_row) * 128 + b_col);
        __syncthreads();
#pragma unroll
        for (int k = 0; k < 8; k++) {
            float4 a0 = *reinterpret_cast<const float4*>(&As[k][ty * 8]);
            float4 a1 = *reinterpret_cast<const float4*>(&As[k][ty * 8 + 4]);
            unsigned long long b2[4];
#pragma unroll
            for (int j = 0; j < 4; j++)
                b2[j] = *reinterpret_cast<const unsigned long long*>(&Bs[k][tx * 8 + 2 * j]);
            float af[8] = {a0.x, a0.y, a0.z, a0.w, a1.x, a1.y, a1.z, a1.w};
#pragma unroll
            for (int i = 0; i < 8; i++) {
                unsigned long long a2 = pk2(af[i], af[i]);
#pragma unroll
                for (int j = 0; j < 4; j++)
                    fma2(acc2[i][j], a2, b2[j]);
            }
        }
        __syncthreads();
    }

#pragma unroll
    for (int i = 0; i < 8; i++) {
        int gm = bm + ty * 8 + i;
        if (gm >= M) continue;
        float d = g_dis[gm];
        float c[8];
#pragma unroll
        for (int j = 0; j < 4; j++) upk2(acc2[i][j], c[2 * j], c[2 * j + 1]);
        float* op = out + (size_t)gm * 128 + tx * 8;
        float4 v0, v1;
        v0.x = d * c[0]; v0.y = d * c[1]; v0.z = d * c[2]; v0.w = d * c[3];
        v1.x = d * c[4]; v1.y = d * c[5]; v1.z = d * c[6]; v1.w = d * c[7];
        *reinterpret_cast<float4*>(op)     = v0;
        *reinterpret_cast<float4*>(op + 4) = v1;
    }
}

// ---------------- aggregation D=128: one warp per node -----------------------
// out[i] = maybe_relu( dis[i] * (g[i] + sum_{s in adj(i)} g[s]) + b )
__global__ __launch_bounds__(256)
void agg128_k(const float* __restrict__ g, const float* __restrict__ b,
              float* __restrict__ out, int n, int relu) {
    int warp = (blockIdx.x * blockDim.x + threadIdx.x) >> 5;
    int lane = threadIdx.x & 31;
    if (warp >= n) return;

    float4 acc = *(reinterpret_cast<const float4*>(g + (size_t)warp * 128) + lane); // self loop
    int start = g_rowptr[warp];
    int c     = g_cnt[warp];
    int i = 0;
    for (; i + 4 <= c; i += 4) {
        int s0 = g_col[start + i];
        int s1 = g_col[start + i + 1];
        int s2 = g_col[start + i + 2];
        int s3 = g_col[start + i + 3];
        float4 v0 = *(reinterpret_cast<const float4*>(g + (size_t)s0 * 128) + lane);
        float4 v1 = *(reinterpret_cast<const float4*>(g + (size_t)s1 * 128) + lane);
        float4 v2 = *(reinterpret_cast<const float4*>(g + (size_t)s2 * 128) + lane);
        float4 v3 = *(reinterpret_cast<const float4*>(g + (size_t)s3 * 128) + lane);
        acc.x += (v0.x + v1.x) + (v2.x + v3.x);
        acc.y += (v0.y + v1.y) + (v2.y + v3.y);
        acc.z += (v0.z + v1.z) + (v2.z + v3.z);
        acc.w += (v0.w + v1.w) + (v2.w + v3.w);
    }
    for (; i < c; i++) {
        int s = g_col[start + i];
        float4 v = *(reinterpret_cast<const float4*>(g + (size_t)s * 128) + lane);
        acc.x += v.x; acc.y += v.y; acc.z += v.z; acc.w += v.w;
    }
    float d = g_dis[warp];
    float4 bb = *(reinterpret_cast<const float4*>(b) + lane);
    float4 r;
    r.x = fmaf(d, acc.x, bb.x);
    r.y = fmaf(d, acc.y, bb.y);
    r.z = fmaf(d, acc.z, bb.z);
    r.w = fmaf(d, acc.w, bb.w);
    if (relu) {
        r.x = fmaxf(r.x, 0.f); r.y = fmaxf(r.y, 0.f);
        r.z = fmaxf(r.z, 0.f); r.w = fmaxf(r.w, 0.f);
    }
    *(reinterpret_cast<float4*>(out + (size_t)warp * 128) + lane) = r;
}

// ---------------- GEMM small: out[m,:] = dis[m]*(A[m,:] @ W3), Nout=16 -------
__global__ __launch_bounds__(256)
void gemm16_k(const float* __restrict__ A, const float* __restrict__ W,
              float* __restrict__ out, int M) {
    __shared__ float in_s[64][132];
    __shared__ float Ws[128 * 16];
    int t  = threadIdx.x;
    int br = blockIdx.x * 64;
#pragma unroll
    for (int i = 0; i < 8; i++) Ws[t + 256 * i] = W[t + 256 * i];
#pragma unroll
    for (int it = 0; it < 8; it++) {
        int flat = t + 256 * it;          // float4 index
        int row = flat >> 5, c4 = flat & 31;
        int gm = br + row;
        float4 v = make_float4(0.f, 0.f, 0.f, 0.f);
        if (gm < M) v = *(reinterpret_cast<const float4*>(A + (size_t)gm * 128) + c4);
        *reinterpret_cast<float4*>(&in_s[row][c4 * 4]) = v;
    }
    __syncthreads();
    int r = t >> 2, nq = (t & 3) * 4;
    int gm = br + r;
    float4 acc = make_float4(0.f, 0.f, 0.f, 0.f);
#pragma unroll
    for (int k = 0; k < 128; k++) {
        float a = in_s[r][k];
        float4 w = *reinterpret_cast<const float4*>(&Ws[k * 16 + nq]);
        acc.x = fmaf(a, w.x, acc.x);
        acc.y = fmaf(a, w.y, acc.y);
        acc.z = fmaf(a, w.z, acc.z);
        acc.w = fmaf(a, w.w, acc.w);
    }
    if (gm < M) {
        float d = g_dis[gm];
        float4 o;
        o.x = d * acc.x; o.y = d * acc.y; o.z = d * acc.z; o.w = d * acc.w;
        *reinterpret_cast<float4*>(out + (size_t)gm * 16 + nq) = o;
    }
}

// ---------------- aggregation D=16: 4 threads per node (no relu) -------------
__global__ __launch_bounds__(256)
void agg16_k(const float* __restrict__ g, const float* __restrict__ b,
             float* __restrict__ out, int n) {
    int gt = blockIdx.x * blockDim.x + threadIdx.x;
    int node = gt >> 2, q = gt & 3;
    if (node >= n) return;
    float4 acc = *reinterpret_cast<const float4*>(g + (size_t)node * 16 + q * 4); // self loop
    int start = g_rowptr[node];
    int c     = g_cnt[node];
    for (int i = 0; i < c; i++) {
        int s = g_col[start + i];
        float4 v = *reinterpret_cast<const float4*>(g + (size_t)s * 16 + q * 4);
        acc.x += v.x; acc.y += v.y; acc.z += v.z; acc.w += v.w;
    }
    float d = g_dis[node];
    float4 bb = *reinterpret_cast<const float4*>(b + q * 4);
    float4 r;
    r.x = fmaf(d, acc.x, bb.x);
    r.y = fmaf(d, acc.y, bb.y);
    r.z = fmaf(d, acc.z, bb.z);
    r.w = fmaf(d, acc.w, bb.w);
    *reinterpret_cast<float4*>(out + (size_t)node * 16 + q * 4) = r;
}

// ---------------- launch ------------------------------------------------------
extern "C" void kernel_launch(void* const* d_in, const int* in_sizes, int n_in,
                              void* d_out, int out_size) {
    const float* x  = (const float*)d_in[0];
    const int*   ei = (const int*)d_in[1];
    const float* W1 = (const float*)d_in[2];
    const float* b1 = (const float*)d_in[3];
    const float* W2 = (const float*)d_in[4];
    const float* b2 = (const float*)d_in[5];
    const float* W3 = (const float*)d_in[6];
    const float* b3 = (const float*)d_in[7];
    float* out = (float*)d_out;

    int n = in_sizes[0] / 128;   // 100000
    int e = in_sizes[1] / 2;     // 1600000
    const int* src = ei;
    const int* dst = ei + e;

    float *buf0, *buf1, *buf3;
    cudaGetSymbolAddress((void**)&buf0, g_buf0);
    cudaGetSymbolAddress((void**)&buf1, g_buf1);
    cudaGetSymbolAddress((void**)&buf3, g_buf3);

    int nb512 = (n + 511) / 512;

    // CSR build + normalization
    init_k <<<(n + 255) / 256, 256>>>(n);
    count_k<<<(e + 255) / 256, 256>>>(dst, e);
    scan1_k<<<nb512, 512>>>(n);
    scan2_k<<<1, 256>>>(nb512);
    scan3_k<<<nb512, 512>>>(n);
    dis_k  <<<(n + 255) / 256, 256>>>(n);
    fill_k <<<(e + 255) / 256, 256>>>(src, dst, e);

    // Layer 1
    gemm128_k<<<(n + 127) / 128, 256>>>(x, W1, buf0, n);
    agg128_k <<<(n + 7) / 8, 256>>>(buf0, b1, buf1, n, 1);
    // Layer 2
    gemm128_k<<<(n + 127) / 128, 256>>>(buf1, W2, buf0, n);
    agg128_k <<<(n + 7) / 8, 256>>>(buf0, b2, buf1, n, 1);
    // Layer 3
    gemm16_k <<<(n + 63) / 64, 256>>>(buf1, W3, buf3, n);
    agg16_k  <<<(n * 4 + 255) / 256, 256>>>(buf3, b3, out, n);
}

// round 4
// speedup vs baseline: 1.0248x; 1.0188x over previous
#include <cuda_runtime.h>

// Problem constants (fixed-shape problem; runtime values derived from in_sizes)
#define NMAX 100000
#define EMAX 1600000

// ---------------- device scratch (static: no allocation allowed) -------------
__device__ int   g_cnt[NMAX];        // in-degree (excl self loop)
__device__ int   g_cursor[NMAX];     // CSR fill cursors (seeded = rowptr)
__device__ int   g_rowptr[NMAX];     // exclusive prefix of g_cnt
__device__ float g_dis[NMAX];        // rsqrt(deg) with deg = indeg+1
__device__ int   g_col[EMAX];        // CSR column (src) indices
__device__ int   g_partials[256];    // scan partials
__device__ float g_buf0[(size_t)NMAX * 128];
__device__ float g_buf1[(size_t)NMAX * 128];
__device__ float g_buf3[(size_t)NMAX * 16];

// ---------------- packed fp32x2 helpers (Blackwell FFMA2 pipe) ---------------
__device__ __forceinline__ unsigned long long pk2(float x, float y) {
    unsigned long long r;
    asm("mov.b64 %0, {%1, %2};" : "=l"(r) : "f"(x), "f"(y));
    return r;
}
__device__ __forceinline__ void fma2(unsigned long long& d,
                                     unsigned long long a, unsigned long long b) {
    asm("fma.rn.f32x2 %0, %1, %2, %0;" : "+l"(d) : "l"(a), "l"(b));
}
__device__ __forceinline__ void upk2(unsigned long long v, float& x, float& y) {
    asm("mov.b64 {%0, %1}, %2;" : "=f"(x), "=f"(y) : "l"(v));
}

// ---------------- graph preprocessing ----------------------------------------
__global__ void init_k(int n) {
    int i = blockIdx.x * blockDim.x + threadIdx.x;
    if (i < n) g_cnt[i] = 0;
}

__global__ void count_k(const int* __restrict__ dst, int e) {
    int i = blockIdx.x * blockDim.x + threadIdx.x;
    if (i < e) atomicAdd(&g_cnt[dst[i]], 1);
}

// block-wise exclusive scan, 512 elems/block
__global__ void scan1_k(int n) {
    __shared__ int s[512];
    int tid = threadIdx.x;
    int i = blockIdx.x * 512 + tid;
    int v = (i < n) ? g_cnt[i] : 0;
    s[tid] = v;
    __syncthreads();
    for (int off = 1; off < 512; off <<= 1) {
        int t = (tid >= off) ? s[tid - off] : 0;
        __syncthreads();
        s[tid] += t;
        __syncthreads();
    }
    if (i < n) g_rowptr[i] = s[tid] - v;       // exclusive within block
    if (tid == 511) g_partials[blockIdx.x] = s[511];
}

__global__ void scan2_k(int nb) {
    __shared__ int s[256];
    int tid = threadIdx.x;
    int v = (tid < nb) ? g_partials[tid] : 0;
    s[tid] = v;
    __syncthreads();
    for (int off = 1; off < 256; off <<= 1) {
        int t = (tid >= off) ? s[tid - off] : 0;
        __syncthreads();
        s[tid] += t;
        __syncthreads();
    }
    if (tid < nb) g_partials[tid] = s[tid] - v;  // exclusive block offsets
}

// finalize rowptr, seed cursor, compute dis — one pass
__global__ void scan3_dis_k(int n) {
    int i = blockIdx.x * 512 + threadIdx.x;
    if (i < n) {
        int rp = g_rowptr[i] + g_partials[blockIdx.x];
        g_rowptr[i] = rp;
        g_cursor[i] = rp;
        g_dis[i]    = rsqrtf((float)(g_cnt[i] + 1));   // +1: self loop
    }
}

__global__ void fill_k(const int* __restrict__ src, const int* __restrict__ dst, int e) {
    int i = blockIdx.x * blockDim.x + threadIdx.x;
    if (i < e) {
        int p = atomicAdd(&g_cursor[dst[i]], 1);
        g_col[p] = src[i];
    }
}

// ---------------- GEMM: out = A @ W (K=128, Nout=128), no epilogue scaling ---
// 128x128 blocktile, 8x8 per-thread tile as 8x4 packed f32x2 accumulators.
// Software-pipelined: next tile's global loads issued before compute.
__global__ __launch_bounds__(256)
void gemm128_k(const float* __restrict__ A, const float* __restrict__ W,
               float* __restrict__ out, int M) {
    __shared__ float As[8][132];   // [BK][BM+pad] (transposed A)
    __shared__ float Bs[8][128];   // [BK][BN]
    const int t  = threadIdx.x;
    const int bm = blockIdx.x * 128;
    const int a_row = t >> 1, a_col = (t & 1) * 4;
    const int b_row = t >> 5, b_col = (t & 31) * 4;
    const int tx = t & 15, ty = t >> 4;
    const int gm_a = bm + a_row;
    const bool a_ok = (gm_a < M);
    const float* a_ptr = A + (size_t)gm_a * 128 + a_col;
    const float* b_ptr = W + (size_t)b_row * 128 + b_col;

    unsigned long long acc2[8][4];
#pragma unroll
    for (int i = 0; i < 8; i++)
#pragma unroll
        for (int j = 0; j < 4; j++) acc2[i][j] = 0ULL;

    // preload tile 0
    float4 av = make_float4(0.f, 0.f, 0.f, 0.f);
    if (a_ok) av = *reinterpret_cast<const float4*>(a_ptr);
    float4 bv = *reinterpret_cast<const float4*>(b_ptr);
    As[a_col + 0][a_row] = av.x;
    As[a_col + 1][a_row] = av.y;
    As[a_col + 2][a_row] = av.z;
    As[a_col + 3][a_row] = av.w;
    *reinterpret_cast<float4*>(&Bs[b_row][b_col]) = bv;

    for (int k0 = 0; k0 < 128; k0 += 8) {
        __syncthreads();   // tile ready
        // prefetch next tile into registers (hide L2 latency behind compute)
        if (k0 + 8 < 128) {
            av = make_float4(0.f, 0.f, 0.f, 0.f);
            if (a_ok) av = *reinterpret_cast<const float4*>(a_ptr + k0 + 8);
            bv = *reinterpret_cast<const float4*>(b_ptr + (size_t)(k0 + 8) * 128);
        }
#pragma unroll
        for (int k = 0; k < 8; k++) {
            float4 a0 = *reinterpret_cast<const float4*>(&As[k][ty * 8]);
            float4 a1 = *reinterpret_cast<const float4*>(&As[k][ty * 8 + 4]);
            unsigned long long b2[4];
#pragma unroll
            for (int j = 0; j < 4; j++)
                b2[j] = *reinterpret_cast<const unsigned long long*>(&Bs[k][tx * 8 + 2 * j]);
            float af[8] = {a0.x, a0.y, a0.z, a0.w, a1.x, a1.y, a1.z, a1.w};
#pragma unroll
            for (int i = 0; i < 8; i++) {
                unsigned long long a2 = pk2(af[i], af[i]);
#pragma unroll
                for (int j = 0; j < 4; j++)
                    fma2(acc2[i][j], a2, b2[j]);
            }
        }
        __syncthreads();   // everyone done reading
        if (k0 + 8 < 128) {
            As[a_col + 0][a_row] = av.x;
            As[a_col + 1][a_row] = av.y;
            As[a_col + 2][a_row] = av.z;
            As[a_col + 3][a_row] = av.w;
            *reinterpret_cast<float4*>(&Bs[b_row][b_col]) = bv;
        }
    }

#pragma unroll
    for (int i = 0; i < 8; i++) {
        int gm = bm + ty * 8 + i;
        if (gm >= M) continue;
        float c[8];
#pragma unroll
        for (int j = 0; j < 4; j++) upk2(acc2[i][j], c[2 * j], c[2 * j + 1]);
        float* op = out + (size_t)gm * 128 + tx * 8;
        *reinterpret_cast<float4*>(op)     = make_float4(c[0], c[1], c[2], c[3]);
        *reinterpret_cast<float4*>(op + 4) = make_float4(c[4], c[5], c[6], c[7]);
    }
}

// ---------------- aggregation D=128: one warp per node -----------------------
// out[d] = maybe_relu( dis[d] * (dis[d]*g[d] + sum_s dis[s]*g[s]) + b )
__global__ __launch_bounds__(256)
void agg128_k(const float* __restrict__ g, const float* __restrict__ b,
              float* __restrict__ out, int n, int relu) {
    int warp = (blockIdx.x * blockDim.x + threadIdx.x) >> 5;
    int lane = threadIdx.x & 31;
    if (warp >= n) return;

    float dd = g_dis[warp];
    float4 self = *(reinterpret_cast<const float4*>(g + (size_t)warp * 128) + lane);
    float4 acc;
    acc.x = dd * self.x; acc.y = dd * self.y; acc.z = dd * self.z; acc.w = dd * self.w;

    int start = g_rowptr[warp];
    int c     = g_cnt[warp];
    int i = 0;
    for (; i + 8 <= c; i += 8) {
        int   s[8];
        float ds[8];
#pragma unroll
        for (int u = 0; u < 8; u++) s[u] = g_col[start + i + u];
#pragma unroll
        for (int u = 0; u < 8; u++) ds[u] = g_dis[s[u]];
#pragma unroll
        for (int u = 0; u < 8; u++) {
            float4 v = *(reinterpret_cast<const float4*>(g + (size_t)s[u] * 128) + lane);
            acc.x = fmaf(ds[u], v.x, acc.x);
            acc.y = fmaf(ds[u], v.y, acc.y);
            acc.z = fmaf(ds[u], v.z, acc.z);
            acc.w = fmaf(ds[u], v.w, acc.w);
        }
    }
    for (; i < c; i++) {
        int s = g_col[start + i];
        float ds = g_dis[s];
        float4 v = *(reinterpret_cast<const float4*>(g + (size_t)s * 128) + lane);
        acc.x = fmaf(ds, v.x, acc.x);
        acc.y = fmaf(ds, v.y, acc.y);
        acc.z = fmaf(ds, v.z, acc.z);
        acc.w = fmaf(ds, v.w, acc.w);
    }
    float4 bb = *(reinterpret_cast<const float4*>(b) + lane);
    float4 r;
    r.x = fmaf(dd, acc.x, bb.x);
    r.y = fmaf(dd, acc.y, bb.y);
    r.z = fmaf(dd, acc.z, bb.z);
    r.w = fmaf(dd, acc.w, bb.w);
    if (relu) {
        r.x = fmaxf(r.x, 0.f); r.y = fmaxf(r.y, 0.f);
        r.z = fmaxf(r.z, 0.f); r.w = fmaxf(r.w, 0.f);
    }
    *(reinterpret_cast<float4*>(out + (size_t)warp * 128) + lane) = r;
}

// ---------------- GEMM small: out = A @ W3 (Nout=16), no scaling -------------
__global__ __launch_bounds__(256)
void gemm16_k(const float* __restrict__ A, const float* __restrict__ W,
              float* __restrict__ out, int M) {
    __shared__ float in_s[64][132];
    __shared__ float Ws[128 * 16];
    int t  = threadIdx.x;
    int br = blockIdx.x * 64;
#pragma unroll
    for (int i = 0; i < 8; i++) Ws[t + 256 * i] = W[t + 256 * i];
#pragma unroll
    for (int it = 0; it < 8; it++) {
        int flat = t + 256 * it;          // float4 index
        int row = flat >> 5, c4 = flat & 31;
        int gm = br + row;
        float4 v = make_float4(0.f, 0.f, 0.f, 0.f);
        if (gm < M) v = *(reinterpret_cast<const float4*>(A + (size_t)gm * 128) + c4);
        *reinterpret_cast<float4*>(&in_s[row][c4 * 4]) = v;
    }
    __syncthreads();
    int r = t >> 2, nq = (t & 3) * 4;
    int gm = br + r;
    float4 acc = make_float4(0.f, 0.f, 0.f, 0.f);
#pragma unroll
    for (int k = 0; k < 128; k++) {
        float a = in_s[r][k];
        float4 w = *reinterpret_cast<const float4*>(&Ws[k * 16 + nq]);
        acc.x = fmaf(a, w.x, acc.x);
        acc.y = fmaf(a, w.y, acc.y);
        acc.z = fmaf(a, w.z, acc.z);
        acc.w = fmaf(a, w.w, acc.w);
    }
    if (gm < M)
        *reinterpret_cast<float4*>(out + (size_t)gm * 16 + nq) = acc;
}

// ---------------- aggregation D=16: 4 threads per node (no relu) -------------
__global__ __launch_bounds__(256)
void agg16_k(const float* __restrict__ g, const float* __restrict__ b,
             float* __restrict__ out, int n) {
    int gt = blockIdx.x * blockDim.x + threadIdx.x;
    int node = gt >> 2, q = gt & 3;
    if (node >= n) return;
    float dd = g_dis[node];
    float4 self = *reinterpret_cast<const float4*>(g + (size_t)node * 16 + q * 4);
    float4 acc;
    acc.x = dd * self.x; acc.y = dd * self.y; acc.z = dd * self.z; acc.w = dd * self.w;
    int start = g_rowptr[node];
    int c     = g_cnt[node];
    for (int i = 0; i < c; i++) {
        int s = g_col[start + i];
        float ds = g_dis[s];
        float4 v = *reinterpret_cast<const float4*>(g + (size_t)s * 16 + q * 4);
        acc.x = fmaf(ds, v.x, acc.x);
        acc.y = fmaf(ds, v.y, acc.y);
        acc.z = fmaf(ds, v.z, acc.z);
        acc.w = fmaf(ds, v.w, acc.w);
    }
    float4 bb = *reinterpret_cast<const float4*>(b + q * 4);
    float4 r;
    r.x = fmaf(dd, acc.x, bb.x);
    r.y = fmaf(dd, acc.y, bb.y);
    r.z = fmaf(dd, acc.z, bb.z);
    r.w = fmaf(dd, acc.w, bb.w);
    *reinterpret_cast<float4*>(out + (size_t)node * 16 + q * 4) = r;
}

// ---------------- launch ------------------------------------------------------
extern "C" void kernel_launch(void* const* d_in, const int* in_sizes, int n_in,
                              void* d_out, int out_size) {
    const float* x  = (const float*)d_in[0];
    const int*   ei = (const int*)d_in[1];
    const float* W1 = (const float*)d_in[2];
    const float* b1 = (const float*)d_in[3];
    const float* W2 = (const float*)d_in[4];
    const float* b2 = (const float*)d_in[5];
    const float* W3 = (const float*)d_in[6];
    const float* b3 = (const float*)d_in[7];
    float* out = (float*)d_out;

    int n = in_sizes[0] / 128;   // 100000
    int e = in_sizes[1] / 2;     // 1600000
    const int* src = ei;
    const int* dst = ei + e;

    float *buf0, *buf1, *buf3;
    cudaGetSymbolAddress((void**)&buf0, g_buf0);
    cudaGetSymbolAddress((void**)&buf1, g_buf1);
    cudaGetSymbolAddress((void**)&buf3, g_buf3);

    // one-time host resources (created on the correctness call, before capture)
    static cudaStream_t s2 = nullptr;
    static cudaEvent_t  ev_fork = nullptr, ev_join = nullptr;
    if (s2 == nullptr) {
        cudaStreamCreateWithFlags(&s2, cudaStreamNonBlocking);
        cudaEventCreateWithFlags(&ev_fork, cudaEventDisableTiming);
        cudaEventCreateWithFlags(&ev_join, cudaEventDisableTiming);
    }

    int nb512 = (n + 511) / 512;

    // Fork: CSR build on s2, gemm1 (independent of graph) on main stream.
    cudaEventRecord(ev_fork, 0);
    cudaStreamWaitEvent(s2, ev_fork, 0);

    init_k     <<<(n + 255) / 256, 256, 0, s2>>>(n);
    count_k    <<<(e + 255) / 256, 256, 0, s2>>>(dst, e);
    scan1_k    <<<nb512, 512, 0, s2>>>(n);
    scan2_k    <<<1, 256, 0, s2>>>(nb512);
    scan3_dis_k<<<nb512, 512, 0, s2>>>(n);
    fill_k     <<<(e + 255) / 256, 256, 0, s2>>>(src, dst, e);
    cudaEventRecord(ev_join, s2);

    gemm128_k<<<(n + 127) / 128, 256>>>(x, W1, buf0, n);

    // Join: aggregation needs both gemm1 output and the CSR.
    cudaStreamWaitEvent(0, ev_join, 0);

    agg128_k <<<(n + 7) / 8, 256>>>(buf0, b1, buf1, n, 1);
    gemm128_k<<<(n + 127) / 128, 256>>>(buf1, W2, buf0, n);
    agg128_k <<<(n + 7) / 8, 256>>>(buf0, b2, buf1, n, 1);
    gemm16_k <<<(n + 63) / 64, 256>>>(buf1, W3, buf3, n);
    agg16_k  <<<(n * 4 + 255) / 256, 256>>>(buf3, b3, out, n);
}